// round 14
// baseline (speedup 1.0000x reference)
#include <cuda_runtime.h>
#include <cuda.h>
#include <cuda_fp16.h>
#include <cstdint>
#include <cstddef>

// ============================================================================
// KAN layer as one fp16 dense GEMM (portable sm_100 path: TMA + ldmatrix +
// mma.sync.m16n8k16). mma.sp is ALU-emulated on this target (R10) -> dense.
//   out[m,o] = x@bw^T + sum_j hat_j(clamp(x)) T_j  (12-knot basis -> 6 knots)
// Partition of unity (sum hat_j = 1) -> T0 becomes a per-o fp32 bias, K=6/input:
// A: (8192 x 6144) fp16 [x, hat1..hat5] ; W: (1024 x 6144) [bw, T1-T0..T5-T0]
// R14: resubmit of R13 (R12's measured ~274us producer/consumer GEMM + R9's
// measured 13.2/14us separate prologues). R13's container error was broker
// flake: the identical GEMM passed in R12, the identical prologues in R9.
// Only change: tensormap prefetch in the producer (cold-descriptor stall).
// ============================================================================

#define INF_   1024
#define OUTF_  1024
#define MTOT   8192
#define KD     6144            // 6 * 1024
#define BM     128
#define BN     128
#define BK     64
#define KT     (KD / BK)       // 96
#define STG    3
#define ASZ    (BM * BK * 2)   // 16384
#define BSZ    (BN * BK * 2)   // 16384
#define STAGEB (ASZ + BSZ)     // 32768
#define HDR    1024
#define SMEMSZ (1024 + HDR + STG * STAGEB)

__device__ __align__(1024) __half g_A[(size_t)MTOT * KD];   // 96 MB
__device__ __align__(1024) __half g_W[(size_t)OUTF_ * KD];  // 12 MB
__device__ float g_biasp[4096];
__device__ float g_bias[1024];

// ---------------------------------------------------------------------------
// helpers
// ---------------------------------------------------------------------------
__device__ __forceinline__ uint32_t s2u(const void* p) {
    uint32_t a;
    asm("{ .reg .u64 t; cvta.to.shared.u64 t, %1; cvt.u32.u64 %0, t; }"
        : "=r"(a) : "l"(p));
    return a;
}
__device__ __forceinline__ void mbar_init(uint32_t m, uint32_t c) {
    asm volatile("mbarrier.init.shared.b64 [%0], %1;" :: "r"(m), "r"(c) : "memory");
}
__device__ __forceinline__ void fence_async_proxy() {
    asm volatile("fence.proxy.async.shared::cta;" ::: "memory");
}
__device__ __forceinline__ void tm_prefetch(const CUtensorMap* m) {
    asm volatile("prefetch.tensormap [%0];" :: "l"(m));
}
__device__ __forceinline__ void mbar_expect(uint32_t m, uint32_t bytes) {
    asm volatile("mbarrier.arrive.expect_tx.shared.b64 _, [%0], %1;"
                 :: "r"(m), "r"(bytes) : "memory");
}
__device__ __forceinline__ void mbar_arrive(uint32_t m) {
    asm volatile("mbarrier.arrive.shared.b64 _, [%0];" :: "r"(m) : "memory");
}
__device__ __forceinline__ void mbar_wait(uint32_t m, uint32_t ph) {
    uint32_t done;
    do {
        asm volatile(
            "{\n\t.reg .pred p;\n\t"
            "mbarrier.try_wait.parity.acquire.cta.shared::cta.b64 p, [%1], %2, 0x989680;\n\t"
            "selp.b32 %0, 1, 0, p;\n\t}"
            : "=r"(done) : "r"(m), "r"(ph) : "memory");
    } while (!done);
}
__device__ __forceinline__ void tma2d(uint32_t dst, const CUtensorMap* m,
                                      int x, int y, uint32_t mbar) {
    asm volatile(
        "cp.async.bulk.tensor.2d.shared::cta.global.tile.mbarrier::complete_tx::bytes "
        "[%0], [%1, {%2, %3}], [%4];"
        :: "r"(dst), "l"(m), "r"(x), "r"(y), "r"(mbar) : "memory");
}
__device__ __forceinline__ void ldsm4(uint32_t* r, uint32_t a) {
    asm volatile("ldmatrix.sync.aligned.m8n8.x4.shared.b16 {%0,%1,%2,%3}, [%4];"
                 : "=r"(r[0]), "=r"(r[1]), "=r"(r[2]), "=r"(r[3]) : "r"(a));
}
__device__ __forceinline__ void mma16816(float* c, const uint32_t* a, const uint32_t* b) {
    asm volatile(
        "mma.sync.aligned.m16n8k16.row.col.f32.f16.f16.f32 "
        "{%0,%1,%2,%3}, {%4,%5,%6,%7}, {%8,%9}, {%0,%1,%2,%3};"
        : "+f"(c[0]), "+f"(c[1]), "+f"(c[2]), "+f"(c[3])
        : "r"(a[0]), "r"(a[1]), "r"(a[2]), "r"(a[3]), "r"(b[0]), "r"(b[1]));
}

// ---------------------------------------------------------------------------
// build_A: one thread per (m,i). Emits 6 halves [x, hat1..hat5] contiguous.
// Block of 256 pairs -> 3072B staged in smem, flushed as 192 uint4.
// ---------------------------------------------------------------------------
__global__ void __launch_bounds__(256) build_A(const float* __restrict__ x) {
    __shared__ __half st[256 * 6];
    int tid = threadIdx.x;
    size_t p = (size_t)blockIdx.x * 256 + tid;
    float xv = x[p];
    float xc = fminf(fmaxf(xv, -1.0f), 1.0f);
    st[tid * 6] = __float2half_rn(xv);
    #pragma unroll
    for (int j = 1; j <= 5; j++) {
        float knot = 0.4f * (float)j - 1.0f;
        float h = fmaxf(0.0f, 1.0f - fabsf(xc - knot) * 2.5f);
        st[tid * 6 + j] = __float2half_rn(h);
    }
    __syncthreads();
    uint4* dst = reinterpret_cast<uint4*>(
        reinterpret_cast<char*>(g_A) + (size_t)blockIdx.x * 3072);
    const uint4* src = reinterpret_cast<const uint4*>(st);
    if (tid < 192) dst[tid] = src[tid];
}

// ---------------------------------------------------------------------------
// build_W: one thread per (o,i). Emits [bw, T1-T0 .. T5-T0]; block-reduces T0.
// ---------------------------------------------------------------------------
__global__ void __launch_bounds__(256) build_W(const float* __restrict__ sw,
                                               const float* __restrict__ bw) {
    __shared__ __half st[256 * 6];
    __shared__ float red[256];
    int tid = threadIdx.x;
    size_t p = (size_t)blockIdx.x * 256 + tid;
    const float4* s4 = reinterpret_cast<const float4*>(sw + p * 12);
    float4 a = s4[0], b = s4[1], c = s4[2];
    float T0 = a.x + a.y + a.z + a.w;
    float T5 = c.x + c.y + c.z + c.w;
    st[tid * 6 + 0] = __float2half_rn(bw[p]);
    st[tid * 6 + 1] = __float2half_rn(b.x - T0);
    st[tid * 6 + 2] = __float2half_rn(b.y - T0);
    st[tid * 6 + 3] = __float2half_rn(b.z - T0);
    st[tid * 6 + 4] = __float2half_rn(b.w - T0);
    st[tid * 6 + 5] = __float2half_rn(T5 - T0);
    red[tid] = T0;
    __syncthreads();
    #pragma unroll
    for (int s = 128; s > 0; s >>= 1) {
        if (tid < s) red[tid] += red[tid + s];
        __syncthreads();
    }
    if (tid == 0) g_biasp[blockIdx.x] = red[0];
    uint4* dst = reinterpret_cast<uint4*>(
        reinterpret_cast<char*>(g_W) + (size_t)blockIdx.x * 3072);
    const uint4* src = reinterpret_cast<const uint4*>(st);
    if (tid < 192) dst[tid] = src[tid];
}

__global__ void sum_bias() {
    int o = blockIdx.x * 256 + threadIdx.x;
    g_bias[o] = g_biasp[o * 4] + g_biasp[o * 4 + 1]
              + g_biasp[o * 4 + 2] + g_biasp[o * 4 + 3];
}

// ---------------------------------------------------------------------------
// GEMM: out = A(8192x6144) @ W(1024x6144)^T + bias, fp16 in, fp32 reg accum.
// 288 threads: warps 0-7 consume (2Mx4N, warp tile 64x32), warp 8 produces.
// Per-stage mbarriers: full[s] (TMA tx, count 1) at sbA+8s; empty[s]
// (8 consumer-warp arrivals) at sbA+32+8s. No CTA barrier in the mainloop.
// blockIdx.x = N tile (fast) so concurrent CTAs share the A tile in L2.
// ---------------------------------------------------------------------------
__global__ void __launch_bounds__(288, 2) kan_gemm(
        const __grid_constant__ CUtensorMap tmA,
        const __grid_constant__ CUtensorMap tmB,
        float* __restrict__ out) {
    extern __shared__ unsigned char smem[];
    uint32_t sbA = (s2u(smem) + 1023u) & ~1023u;
    uint32_t SD = sbA + HDR;
    int tid = threadIdx.x;
    int wid = tid >> 5, lid = tid & 31;
    int n0 = blockIdx.x * BN;
    int m0 = blockIdx.y * BM;

    // init by the SAME thread that issues the TMAs (async-proxy ordering),
    // then fence + CTA barrier before anyone uses the barriers.
    if (tid == 256) {
        tm_prefetch(&tmA);
        tm_prefetch(&tmB);
        #pragma unroll
        for (int s = 0; s < STG; s++) {
            mbar_init(sbA + 8 * s, 1);        // full
            mbar_init(sbA + 32 + 8 * s, 8);   // empty: 8 consumer warps
        }
        fence_async_proxy();
    }
    __syncthreads();

    if (tid == 256) {
        // ---------------- producer (lane 0 of warp 8) ----------------
        #pragma unroll
        for (int s = 0; s < STG; s++) {       // rounds 0..2: no empty wait
            uint32_t fm = sbA + 8 * s;
            uint32_t ds = SD + s * STAGEB;
            mbar_expect(fm, STAGEB);
            tma2d(ds,       &tmA, s * BK, m0, fm);
            tma2d(ds + ASZ, &tmB, s * BK, n0, fm);
        }
        int s = 0, er = 0;                    // empty parity cursor
        for (int itp = STG; itp < KT; ++itp) {
            mbar_wait(sbA + 32 + 8 * s, er);  // consumers released round r-1
            uint32_t fm = sbA + 8 * s;
            uint32_t ds = SD + s * STAGEB;
            mbar_expect(fm, STAGEB);
            tma2d(ds,       &tmA, itp * BK, m0, fm);
            tma2d(ds + ASZ, &tmB, itp * BK, n0, fm);
            if (++s == STG) { s = 0; er ^= 1; }
        }
    } else if (wid < 8) {
        // ---------------- consumers: free-running ----------------
        int wm = (wid >> 2) * 64;
        int wn = (wid & 3) * 32;
        int mi = lid >> 3;
        int lr = lid & 7;

        float acc[4][4][4] = {};

        int s = 0, ph = 0;
        for (int it = 0; it < KT; ++it) {
            mbar_wait(sbA + 8 * s, ph);
            uint32_t asB = SD + s * STAGEB;
            uint32_t bsB = asB + ASZ;
            #pragma unroll
            for (int ks = 0; ks < 4; ++ks) {
                uint32_t aF[4][4], bF[2][4];
                #pragma unroll
                for (int a = 0; a < 4; a++) {
                    int mr = wm + a * 16 + lr + (mi & 1) * 8;
                    int kc = ks * 2 + (mi >> 1);
                    ldsm4(aF[a], asB + mr * 128 + ((kc ^ (mr & 7)) << 4));
                }
                #pragma unroll
                for (int q = 0; q < 2; q++) {
                    int nr = wn + q * 16 + ((mi >> 1) << 3) + lr;
                    int kc = ks * 2 + (mi & 1);
                    ldsm4(bF[q], bsB + nr * 128 + ((kc ^ (nr & 7)) << 4));
                }
                #pragma unroll
                for (int a = 0; a < 4; a++)
                    #pragma unroll
                    for (int b = 0; b < 4; b++)
                        mma16816(acc[a][b], aF[a], &bF[b >> 1][(b & 1) * 2]);
            }
            __syncwarp();
            if (lid == 0) mbar_arrive(sbA + 32 + 8 * s);
            if (++s == STG) { s = 0; ph ^= 1; }
        }

        // epilogue: per-warp, no CTA sync needed
        int row0 = m0 + wm + (lid >> 2);
        int col0 = n0 + wn + (lid & 3) * 2;
        #pragma unroll
        for (int b = 0; b < 4; b++) {
            float bv0 = g_bias[col0 + b * 8];
            float bv1 = g_bias[col0 + b * 8 + 1];
            #pragma unroll
            for (int a = 0; a < 4; a++) {
                float* p0 = out + (size_t)(row0 + a * 16) * OUTF_ + col0 + b * 8;
                float* p1 = p0 + (size_t)8 * OUTF_;
                *reinterpret_cast<float2*>(p0) =
                    make_float2(acc[a][b][0] + bv0, acc[a][b][1] + bv1);
                *reinterpret_cast<float2*>(p1) =
                    make_float2(acc[a][b][2] + bv0, acc[a][b][3] + bv1);
            }
        }
    }
}

// ---------------------------------------------------------------------------
typedef CUresult (CUDAAPI *PFN_tmEncode)(
    CUtensorMap*, CUtensorMapDataType, cuuint32_t, void*,
    const cuuint64_t*, const cuuint64_t*, const cuuint32_t*, const cuuint32_t*,
    CUtensorMapInterleave, CUtensorMapSwizzle, CUtensorMapL2promotion,
    CUtensorMapFloatOOBfill);

extern "C" void kernel_launch(void* const* d_in, const int* in_sizes, int n_in,
                              void* d_out, int out_size) {
    const float* x  = (const float*)d_in[0];   // (4,2048,1024)
    const float* sw = (const float*)d_in[1];   // (1024,1024,12)
    const float* bw = (const float*)d_in[2];   // (1024,1024)
    float* out = (float*)d_out;                // (4,2048,1024)

    CUtensorMap tmA, tmB;
    PFN_tmEncode enc = nullptr;
    cudaDriverEntryPointQueryResult qr = cudaDriverEntryPointSymbolNotFound;
    cudaGetDriverEntryPoint("cuTensorMapEncodeTiled", (void**)&enc,
                            cudaEnableDefault, &qr);
    void *pA = nullptr, *pW = nullptr;
    cudaGetSymbolAddress(&pA, g_A);
    cudaGetSymbolAddress(&pW, g_W);

    cuuint64_t dimsA[2] = {KD, MTOT};
    cuuint64_t strA[1]  = {KD * 2};
    cuuint32_t boxA[2]  = {BK, BM};
    cuuint32_t el[2]    = {1, 1};
    enc(&tmA, CU_TENSOR_MAP_DATA_TYPE_FLOAT16, 2, pA, dimsA, strA, boxA, el,
        CU_TENSOR_MAP_INTERLEAVE_NONE, CU_TENSOR_MAP_SWIZZLE_128B,
        CU_TENSOR_MAP_L2_PROMOTION_L2_128B, CU_TENSOR_MAP_FLOAT_OOB_FILL_NONE);

    cuuint64_t dimsB[2] = {KD, OUTF_};
    cuuint64_t strB[1]  = {KD * 2};
    cuuint32_t boxB[2]  = {BK, BN};
    enc(&tmB, CU_TENSOR_MAP_DATA_TYPE_FLOAT16, 2, pW, dimsB, strB, boxB, el,
        CU_TENSOR_MAP_INTERLEAVE_NONE, CU_TENSOR_MAP_SWIZZLE_128B,
        CU_TENSOR_MAP_L2_PROMOTION_L2_128B, CU_TENSOR_MAP_FLOAT_OOB_FILL_NONE);

    cudaFuncSetAttribute(kan_gemm, cudaFuncAttributeMaxDynamicSharedMemorySize, SMEMSZ);

    build_W<<<(OUTF_ * INF_) / 256, 256>>>(sw, bw);
    sum_bias<<<4, 256>>>();
    build_A<<<(MTOT * INF_) / 256, 256>>>(x);
    dim3 grid(OUTF_ / BN, MTOT / BM);   // x = N tile (fast) -> A L2 reuse
    kan_gemm<<<grid, 288, SMEMSZ>>>(tmA, tmB, out);
}

// round 15
// speedup vs baseline: 1.1275x; 1.1275x over previous
#include <cuda_runtime.h>
#include <cuda.h>
#include <cuda_fp16.h>
#include <cstdint>
#include <cstddef>

// ============================================================================
// KAN layer as one fp16 dense GEMM (portable sm_100 path: TMA + ldmatrix +
// mma.sync.m16n8k16).
//   out[m,o] = x@bw^T + sum_j hat_j(clamp(x)) T_j  (12-knot basis -> 6 knots)
// Partition of unity (sum hat_j = 1) -> T0 becomes a per-o fp32 bias, K=6/input:
// A: (8192 x 6144) fp16 [x, hat1..hat5] ; W: (1024 x 6144) [bw, T1-T0..T5-T0]
// R15: attack WAVE QUANTIZATION. R9's measured-best GEMM structure, but
// BN 128->64: 1024 half-size tiles, 3 CTAs/SM (444 slots, 6 warps/SMSP),
// per-SM makespan 3.5 units vs 4.0 (+14%). Warp tile 32x32 (4Mx2N),
// single-buffered fragments to fit the 85-reg cap at occupancy 3.
// ============================================================================

#define INF_   1024
#define OUTF_  1024
#define MTOT   8192
#define KD     6144            // 6 * 1024
#define BM     128
#define BN     64
#define BK     64
#define KT     (KD / BK)       // 96
#define STG    3
#define ASZ    (BM * BK * 2)   // 16384
#define BSZ    (BN * BK * 2)   // 8192
#define STAGEB (ASZ + BSZ)     // 24576
#define HDR    1024
#define SMEMSZ (1024 + HDR + STG * STAGEB)   // 75776 (<= 77824 for 3/SM)

__device__ __align__(1024) __half g_A[(size_t)MTOT * KD];   // 96 MB
__device__ __align__(1024) __half g_W[(size_t)OUTF_ * KD];  // 12 MB
__device__ float g_biasp[4096];
__device__ float g_bias[1024];

// ---------------------------------------------------------------------------
// helpers
// ---------------------------------------------------------------------------
__device__ __forceinline__ uint32_t s2u(const void* p) {
    uint32_t a;
    asm("{ .reg .u64 t; cvta.to.shared.u64 t, %1; cvt.u32.u64 %0, t; }"
        : "=r"(a) : "l"(p));
    return a;
}
__device__ __forceinline__ void mbar_init(uint32_t m, uint32_t c) {
    asm volatile("mbarrier.init.shared.b64 [%0], %1;" :: "r"(m), "r"(c) : "memory");
}
__device__ __forceinline__ void fence_async_proxy() {
    asm volatile("fence.proxy.async.shared::cta;" ::: "memory");
}
__device__ __forceinline__ void tm_prefetch(const CUtensorMap* m) {
    asm volatile("prefetch.tensormap [%0];" :: "l"(m));
}
__device__ __forceinline__ void mbar_expect(uint32_t m, uint32_t bytes) {
    asm volatile("mbarrier.arrive.expect_tx.shared.b64 _, [%0], %1;"
                 :: "r"(m), "r"(bytes) : "memory");
}
__device__ __forceinline__ void mbar_wait(uint32_t m, uint32_t ph) {
    uint32_t done;
    do {
        asm volatile(
            "{\n\t.reg .pred p;\n\t"
            "mbarrier.try_wait.parity.acquire.cta.shared::cta.b64 p, [%1], %2, 0x989680;\n\t"
            "selp.b32 %0, 1, 0, p;\n\t}"
            : "=r"(done) : "r"(m), "r"(ph) : "memory");
    } while (!done);
}
__device__ __forceinline__ void tma2d(uint32_t dst, const CUtensorMap* m,
                                      int x, int y, uint32_t mbar) {
    asm volatile(
        "cp.async.bulk.tensor.2d.shared::cta.global.tile.mbarrier::complete_tx::bytes "
        "[%0], [%1, {%2, %3}], [%4];"
        :: "r"(dst), "l"(m), "r"(x), "r"(y), "r"(mbar) : "memory");
}
__device__ __forceinline__ void ldsm4(uint32_t* r, uint32_t a) {
    asm volatile("ldmatrix.sync.aligned.m8n8.x4.shared.b16 {%0,%1,%2,%3}, [%4];"
                 : "=r"(r[0]), "=r"(r[1]), "=r"(r[2]), "=r"(r[3]) : "r"(a));
}
__device__ __forceinline__ void mma16816(float* c, const uint32_t* a, const uint32_t* b) {
    asm volatile(
        "mma.sync.aligned.m16n8k16.row.col.f32.f16.f16.f32 "
        "{%0,%1,%2,%3}, {%4,%5,%6,%7}, {%8,%9}, {%0,%1,%2,%3};"
        : "+f"(c[0]), "+f"(c[1]), "+f"(c[2]), "+f"(c[3])
        : "r"(a[0]), "r"(a[1]), "r"(a[2]), "r"(a[3]), "r"(b[0]), "r"(b[1]));
}

// ---------------------------------------------------------------------------
// build_A: one thread per (m,i). Emits 6 halves [x, hat1..hat5] contiguous.
// ---------------------------------------------------------------------------
__global__ void __launch_bounds__(256) build_A(const float* __restrict__ x) {
    __shared__ __half st[256 * 6];
    int tid = threadIdx.x;
    size_t p = (size_t)blockIdx.x * 256 + tid;
    float xv = x[p];
    float xc = fminf(fmaxf(xv, -1.0f), 1.0f);
    st[tid * 6] = __float2half_rn(xv);
    #pragma unroll
    for (int j = 1; j <= 5; j++) {
        float knot = 0.4f * (float)j - 1.0f;
        float h = fmaxf(0.0f, 1.0f - fabsf(xc - knot) * 2.5f);
        st[tid * 6 + j] = __float2half_rn(h);
    }
    __syncthreads();
    uint4* dst = reinterpret_cast<uint4*>(
        reinterpret_cast<char*>(g_A) + (size_t)blockIdx.x * 3072);
    const uint4* src = reinterpret_cast<const uint4*>(st);
    if (tid < 192) dst[tid] = src[tid];
}

// ---------------------------------------------------------------------------
// build_W: one thread per (o,i). Emits [bw, T1-T0 .. T5-T0]; block-reduces T0.
// ---------------------------------------------------------------------------
__global__ void __launch_bounds__(256) build_W(const float* __restrict__ sw,
                                               const float* __restrict__ bw) {
    __shared__ __half st[256 * 6];
    __shared__ float red[256];
    int tid = threadIdx.x;
    size_t p = (size_t)blockIdx.x * 256 + tid;
    const float4* s4 = reinterpret_cast<const float4*>(sw + p * 12);
    float4 a = s4[0], b = s4[1], c = s4[2];
    float T0 = a.x + a.y + a.z + a.w;
    float T5 = c.x + c.y + c.z + c.w;
    st[tid * 6 + 0] = __float2half_rn(bw[p]);
    st[tid * 6 + 1] = __float2half_rn(b.x - T0);
    st[tid * 6 + 2] = __float2half_rn(b.y - T0);
    st[tid * 6 + 3] = __float2half_rn(b.z - T0);
    st[tid * 6 + 4] = __float2half_rn(b.w - T0);
    st[tid * 6 + 5] = __float2half_rn(T5 - T0);
    red[tid] = T0;
    __syncthreads();
    #pragma unroll
    for (int s = 128; s > 0; s >>= 1) {
        if (tid < s) red[tid] += red[tid + s];
        __syncthreads();
    }
    if (tid == 0) g_biasp[blockIdx.x] = red[0];
    uint4* dst = reinterpret_cast<uint4*>(
        reinterpret_cast<char*>(g_W) + (size_t)blockIdx.x * 3072);
    const uint4* src = reinterpret_cast<const uint4*>(st);
    if (tid < 192) dst[tid] = src[tid];
}

__global__ void sum_bias() {
    int o = blockIdx.x * 256 + threadIdx.x;
    g_bias[o] = g_biasp[o * 4] + g_biasp[o * 4 + 1]
              + g_biasp[o * 4 + 2] + g_biasp[o * 4 + 3];
}

// ---------------------------------------------------------------------------
// GEMM: out = A(8192x6144) @ W(1024x6144)^T + bias, fp16 in, fp32 reg accum.
// CTA 128x64x64, 3-stage TMA ring, tid0 producer + per-iter __syncthreads
// (R9 structure, measured best). 8 warps 4Mx2N, warp tile 32x32, 3 CTAs/SM.
// blockIdx.x = N tile (fast) so concurrent CTAs share the A tile in L2.
// ---------------------------------------------------------------------------
__global__ void __launch_bounds__(256, 3) kan_gemm(
        const __grid_constant__ CUtensorMap tmA,
        const __grid_constant__ CUtensorMap tmB,
        float* __restrict__ out) {
    extern __shared__ unsigned char smem[];
    uint32_t sbA = (s2u(smem) + 1023u) & ~1023u;
    uint32_t SD = sbA + HDR;
    int tid = threadIdx.x;
    int wid = tid >> 5, lid = tid & 31;
    int n0 = blockIdx.x * BN;
    int m0 = blockIdx.y * BM;

    if (tid == 0) {
        tm_prefetch(&tmA);
        tm_prefetch(&tmB);
        #pragma unroll
        for (int s = 0; s < STG; s++) mbar_init(sbA + 8 * s, 1);
        fence_async_proxy();
    }
    __syncthreads();
    if (tid == 0) {
        #pragma unroll
        for (int s = 0; s < 2; s++) {        // prologue: stages 0,1
            uint32_t fm = sbA + 8 * s;
            uint32_t ds = SD + s * STAGEB;
            mbar_expect(fm, STAGEB);
            tma2d(ds,       &tmA, s * BK, m0, fm);
            tma2d(ds + ASZ, &tmB, s * BK, n0, fm);
        }
    }

    int wm = (wid >> 1) * 32;   // 4 M warp-groups
    int wn = (wid & 1) * 32;    // 2 N warp-groups
    int mi = lid >> 3;          // matrix index within ldsm x4
    int lr = lid & 7;           // row within 8x8 matrix

    float acc[2][4][4] = {};

    int s = 0, phv = 0;         // consumer cursor
    int sp = 2;                 // producer's next stage (tid 0 only)
    for (int it = 0; it < KT; ++it) {
        __syncthreads();        // all reads of the stage being reissued done
        if (tid == 0 && it + 2 < KT) {
            uint32_t fm = sbA + 8 * sp;
            uint32_t ds = SD + sp * STAGEB;
            mbar_expect(fm, STAGEB);
            tma2d(ds,       &tmA, (it + 2) * BK, m0, fm);
            tma2d(ds + ASZ, &tmB, (it + 2) * BK, n0, fm);
            sp = (sp == STG - 1) ? 0 : sp + 1;
        }
        mbar_wait(sbA + 8 * s, phv);

        uint32_t asB = SD + s * STAGEB;
        uint32_t bsB = asB + ASZ;

        #pragma unroll
        for (int ks = 0; ks < 4; ++ks) {
            uint32_t aF[2][4], bF[2][4];
            #pragma unroll
            for (int a = 0; a < 2; a++) {
                int mr = wm + a * 16 + lr + (mi & 1) * 8;
                int kc = ks * 2 + (mi >> 1);
                ldsm4(aF[a], asB + mr * 128 + ((kc ^ (mr & 7)) << 4));
            }
            #pragma unroll
            for (int q = 0; q < 2; q++) {
                int nr = wn + q * 16 + ((mi >> 1) << 3) + lr;
                int kc = ks * 2 + (mi & 1);
                ldsm4(bF[q], bsB + nr * 128 + ((kc ^ (nr & 7)) << 4));
            }
            #pragma unroll
            for (int a = 0; a < 2; a++)
                #pragma unroll
                for (int b = 0; b < 4; b++)
                    mma16816(acc[a][b], aF[a], &bF[b >> 1][(b & 1) * 2]);
        }
        if (++s == STG) { s = 0; phv ^= 1; }
    }

    // epilogue: add fp32 bias, store fp32 tiles
    int row0 = m0 + wm + (lid >> 2);
    int col0 = n0 + wn + (lid & 3) * 2;
    #pragma unroll
    for (int b = 0; b < 4; b++) {
        float bv0 = g_bias[col0 + b * 8];
        float bv1 = g_bias[col0 + b * 8 + 1];
        #pragma unroll
        for (int a = 0; a < 2; a++) {
            float* p0 = out + (size_t)(row0 + a * 16) * OUTF_ + col0 + b * 8;
            float* p1 = p0 + (size_t)8 * OUTF_;
            *reinterpret_cast<float2*>(p0) =
                make_float2(acc[a][b][0] + bv0, acc[a][b][1] + bv1);
            *reinterpret_cast<float2*>(p1) =
                make_float2(acc[a][b][2] + bv0, acc[a][b][3] + bv1);
        }
    }
}

// ---------------------------------------------------------------------------
typedef CUresult (CUDAAPI *PFN_tmEncode)(
    CUtensorMap*, CUtensorMapDataType, cuuint32_t, void*,
    const cuuint64_t*, const cuuint64_t*, const cuuint32_t*, const cuuint32_t*,
    CUtensorMapInterleave, CUtensorMapSwizzle, CUtensorMapL2promotion,
    CUtensorMapFloatOOBfill);

extern "C" void kernel_launch(void* const* d_in, const int* in_sizes, int n_in,
                              void* d_out, int out_size) {
    const float* x  = (const float*)d_in[0];   // (4,2048,1024)
    const float* sw = (const float*)d_in[1];   // (1024,1024,12)
    const float* bw = (const float*)d_in[2];   // (1024,1024)
    float* out = (float*)d_out;                // (4,2048,1024)

    CUtensorMap tmA, tmB;
    PFN_tmEncode enc = nullptr;
    cudaDriverEntryPointQueryResult qr = cudaDriverEntryPointSymbolNotFound;
    cudaGetDriverEntryPoint("cuTensorMapEncodeTiled", (void**)&enc,
                            cudaEnableDefault, &qr);
    void *pA = nullptr, *pW = nullptr;
    cudaGetSymbolAddress(&pA, g_A);
    cudaGetSymbolAddress(&pW, g_W);

    cuuint64_t dimsA[2] = {KD, MTOT};
    cuuint64_t strA[1]  = {KD * 2};
    cuuint32_t boxA[2]  = {BK, BM};
    cuuint32_t el[2]    = {1, 1};
    enc(&tmA, CU_TENSOR_MAP_DATA_TYPE_FLOAT16, 2, pA, dimsA, strA, boxA, el,
        CU_TENSOR_MAP_INTERLEAVE_NONE, CU_TENSOR_MAP_SWIZZLE_128B,
        CU_TENSOR_MAP_L2_PROMOTION_L2_128B, CU_TENSOR_MAP_FLOAT_OOB_FILL_NONE);

    cuuint64_t dimsB[2] = {KD, OUTF_};
    cuuint64_t strB[1]  = {KD * 2};
    cuuint32_t boxB[2]  = {BK, BN};
    enc(&tmB, CU_TENSOR_MAP_DATA_TYPE_FLOAT16, 2, pW, dimsB, strB, boxB, el,
        CU_TENSOR_MAP_INTERLEAVE_NONE, CU_TENSOR_MAP_SWIZZLE_128B,
        CU_TENSOR_MAP_L2_PROMOTION_L2_128B, CU_TENSOR_MAP_FLOAT_OOB_FILL_NONE);

    cudaFuncSetAttribute(kan_gemm, cudaFuncAttributeMaxDynamicSharedMemorySize, SMEMSZ);

    build_W<<<(OUTF_ * INF_) / 256, 256>>>(sw, bw);
    sum_bias<<<4, 256>>>();
    build_A<<<(MTOT * INF_) / 256, 256>>>(x);
    dim3 grid(OUTF_ / BN, MTOT / BM);   // x = N tile (fast, 16) -> A L2 reuse
    kan_gemm<<<grid, 256, SMEMSZ>>>(tmA, tmB, out);
}

// round 17
// speedup vs baseline: 1.1602x; 1.0290x over previous
#include <cuda_runtime.h>
#include <cuda.h>
#include <cuda_fp16.h>
#include <cstdint>
#include <cstddef>

// ============================================================================
// KAN layer as one fp16 dense GEMM (portable sm_100 path: TMA + ldmatrix +
// mma.sync.m16n8k16).
//   out[m,o] = x@bw^T + sum_j hat_j(clamp(x)) T_j  (12-knot basis -> 6 knots)
// Partition of unity (sum hat_j = 1) -> T0 becomes a per-o fp32 bias, K=6/input:
// A: (8192 x 6144) fp16 [x, hat1..hat5] ; W: (1024 x 6144) [bw, T1-T0..T5-T0]
// R17: RESUBMIT of R16 (container flake — same pattern as R13->R14, where the
// identical resubmit passed). R15 measured smem==tensor co-limit (1536 cyc
// each per SM-iter); this kernel keeps R15's CTA tile/occupancy (128x64,
// 3 CTAs/SM, 1024 tiles -> ~99% balance) but uses 4 warps of 64x32 (128 thr):
// 25% less ldsm per MAC -> smem floor 1152 cyc, tensor sole binder.
// Fragment double-buffering (regs ~130 <= 170 cap at 3 CTAs/SM).
// ============================================================================

#define INF_   1024
#define OUTF_  1024
#define MTOT   8192
#define KD     6144            // 6 * 1024
#define BM     128
#define BN     64
#define BK     64
#define KT     (KD / BK)       // 96
#define STG    3
#define ASZ    (BM * BK * 2)   // 16384
#define BSZ    (BN * BK * 2)   // 8192
#define STAGEB (ASZ + BSZ)     // 24576
#define HDR    1024
#define SMEMSZ (1024 + HDR + STG * STAGEB)   // 75776 (3 CTAs/SM)

__device__ __align__(1024) __half g_A[(size_t)MTOT * KD];   // 96 MB
__device__ __align__(1024) __half g_W[(size_t)OUTF_ * KD];  // 12 MB
__device__ float g_biasp[4096];
__device__ float g_bias[1024];

// ---------------------------------------------------------------------------
// helpers
// ---------------------------------------------------------------------------
__device__ __forceinline__ uint32_t s2u(const void* p) {
    uint32_t a;
    asm("{ .reg .u64 t; cvta.to.shared.u64 t, %1; cvt.u32.u64 %0, t; }"
        : "=r"(a) : "l"(p));
    return a;
}
__device__ __forceinline__ void mbar_init(uint32_t m, uint32_t c) {
    asm volatile("mbarrier.init.shared.b64 [%0], %1;" :: "r"(m), "r"(c) : "memory");
}
__device__ __forceinline__ void fence_async_proxy() {
    asm volatile("fence.proxy.async.shared::cta;" ::: "memory");
}
__device__ __forceinline__ void tm_prefetch(const CUtensorMap* m) {
    asm volatile("prefetch.tensormap [%0];" :: "l"(m));
}
__device__ __forceinline__ void mbar_expect(uint32_t m, uint32_t bytes) {
    asm volatile("mbarrier.arrive.expect_tx.shared.b64 _, [%0], %1;"
                 :: "r"(m), "r"(bytes) : "memory");
}
__device__ __forceinline__ void mbar_wait(uint32_t m, uint32_t ph) {
    uint32_t done;
    do {
        asm volatile(
            "{\n\t.reg .pred p;\n\t"
            "mbarrier.try_wait.parity.acquire.cta.shared::cta.b64 p, [%1], %2, 0x989680;\n\t"
            "selp.b32 %0, 1, 0, p;\n\t}"
            : "=r"(done) : "r"(m), "r"(ph) : "memory");
    } while (!done);
}
__device__ __forceinline__ void tma2d(uint32_t dst, const CUtensorMap* m,
                                      int x, int y, uint32_t mbar) {
    asm volatile(
        "cp.async.bulk.tensor.2d.shared::cta.global.tile.mbarrier::complete_tx::bytes "
        "[%0], [%1, {%2, %3}], [%4];"
        :: "r"(dst), "l"(m), "r"(x), "r"(y), "r"(mbar) : "memory");
}
__device__ __forceinline__ void ldsm4(uint32_t* r, uint32_t a) {
    asm volatile("ldmatrix.sync.aligned.m8n8.x4.shared.b16 {%0,%1,%2,%3}, [%4];"
                 : "=r"(r[0]), "=r"(r[1]), "=r"(r[2]), "=r"(r[3]) : "r"(a));
}
__device__ __forceinline__ void mma16816(float* c, const uint32_t* a, const uint32_t* b) {
    asm volatile(
        "mma.sync.aligned.m16n8k16.row.col.f32.f16.f16.f32 "
        "{%0,%1,%2,%3}, {%4,%5,%6,%7}, {%8,%9}, {%0,%1,%2,%3};"
        : "+f"(c[0]), "+f"(c[1]), "+f"(c[2]), "+f"(c[3])
        : "r"(a[0]), "r"(a[1]), "r"(a[2]), "r"(a[3]), "r"(b[0]), "r"(b[1]));
}

// ---------------------------------------------------------------------------
// build_A: one thread per (m,i). Emits 6 halves [x, hat1..hat5] contiguous.
// ---------------------------------------------------------------------------
__global__ void __launch_bounds__(256) build_A(const float* __restrict__ x) {
    __shared__ __half st[256 * 6];
    int tid = threadIdx.x;
    size_t p = (size_t)blockIdx.x * 256 + tid;
    float xv = x[p];
    float xc = fminf(fmaxf(xv, -1.0f), 1.0f);
    st[tid * 6] = __float2half_rn(xv);
    #pragma unroll
    for (int j = 1; j <= 5; j++) {
        float knot = 0.4f * (float)j - 1.0f;
        float h = fmaxf(0.0f, 1.0f - fabsf(xc - knot) * 2.5f);
        st[tid * 6 + j] = __float2half_rn(h);
    }
    __syncthreads();
    uint4* dst = reinterpret_cast<uint4*>(
        reinterpret_cast<char*>(g_A) + (size_t)blockIdx.x * 3072);
    const uint4* src = reinterpret_cast<const uint4*>(st);
    if (tid < 192) dst[tid] = src[tid];
}

// ---------------------------------------------------------------------------
// build_W: one thread per (o,i). Emits [bw, T1-T0 .. T5-T0]; block-reduces T0.
// ---------------------------------------------------------------------------
__global__ void __launch_bounds__(256) build_W(const float* __restrict__ sw,
                                               const float* __restrict__ bw) {
    __shared__ __half st[256 * 6];
    __shared__ float red[256];
    int tid = threadIdx.x;
    size_t p = (size_t)blockIdx.x * 256 + tid;
    const float4* s4 = reinterpret_cast<const float4*>(sw + p * 12);
    float4 a = s4[0], b = s4[1], c = s4[2];
    float T0 = a.x + a.y + a.z + a.w;
    float T5 = c.x + c.y + c.z + c.w;
    st[tid * 6 + 0] = __float2half_rn(bw[p]);
    st[tid * 6 + 1] = __float2half_rn(b.x - T0);
    st[tid * 6 + 2] = __float2half_rn(b.y - T0);
    st[tid * 6 + 3] = __float2half_rn(b.z - T0);
    st[tid * 6 + 4] = __float2half_rn(b.w - T0);
    st[tid * 6 + 5] = __float2half_rn(T5 - T0);
    red[tid] = T0;
    __syncthreads();
    #pragma unroll
    for (int s = 128; s > 0; s >>= 1) {
        if (tid < s) red[tid] += red[tid + s];
        __syncthreads();
    }
    if (tid == 0) g_biasp[blockIdx.x] = red[0];
    uint4* dst = reinterpret_cast<uint4*>(
        reinterpret_cast<char*>(g_W) + (size_t)blockIdx.x * 3072);
    const uint4* src = reinterpret_cast<const uint4*>(st);
    if (tid < 192) dst[tid] = src[tid];
}

__global__ void sum_bias() {
    int o = blockIdx.x * 256 + threadIdx.x;
    g_bias[o] = g_biasp[o * 4] + g_biasp[o * 4 + 1]
              + g_biasp[o * 4 + 2] + g_biasp[o * 4 + 3];
}

// ---------------------------------------------------------------------------
// GEMM: out = A(8192x6144) @ W(1024x6144)^T + bias, fp16 in, fp32 reg accum.
// CTA 128x64x64, 128 threads: 4 warps of 64x32 (2M x 2N), tid0 produces via
// TMA (3-stage ring, per-iter __syncthreads, R15-measured-best structure),
// k16 fragment double-buffering. 3 CTAs/SM.
// blockIdx.x = N tile (fast) so concurrent CTAs share the A tile in L2.
// ---------------------------------------------------------------------------
__global__ void __launch_bounds__(128, 3) kan_gemm(
        const __grid_constant__ CUtensorMap tmA,
        const __grid_constant__ CUtensorMap tmB,
        float* __restrict__ out) {
    extern __shared__ unsigned char smem[];
    uint32_t sbA = (s2u(smem) + 1023u) & ~1023u;
    uint32_t SD = sbA + HDR;
    int tid = threadIdx.x;
    int wid = tid >> 5, lid = tid & 31;
    int n0 = blockIdx.x * BN;
    int m0 = blockIdx.y * BM;

    if (tid == 0) {
        tm_prefetch(&tmA);
        tm_prefetch(&tmB);
        #pragma unroll
        for (int s = 0; s < STG; s++) mbar_init(sbA + 8 * s, 1);
        fence_async_proxy();
    }
    __syncthreads();
    if (tid == 0) {
        #pragma unroll
        for (int s = 0; s < 2; s++) {        // prologue: stages 0,1
            uint32_t fm = sbA + 8 * s;
            uint32_t ds = SD + s * STAGEB;
            mbar_expect(fm, STAGEB);
            tma2d(ds,       &tmA, s * BK, m0, fm);
            tma2d(ds + ASZ, &tmB, s * BK, n0, fm);
        }
    }

    int wm = (wid >> 1) * 64;   // 2 M warp-groups (64 rows each)
    int wn = (wid & 1) * 32;    // 2 N warp-groups (32 cols each)
    int mi = lid >> 3;          // matrix index within ldsm x4
    int lr = lid & 7;           // row within 8x8 matrix

    uint32_t aF[2][4][4], bF[2][2][4];
    #define LDFRAGS(buf, asB_, bsB_, ks_)                                              \
        do {                                                                           \
            _Pragma("unroll")                                                          \
            for (int a_ = 0; a_ < 4; a_++) {                                           \
                int mr_ = wm + a_ * 16 + lr + (mi & 1) * 8;                            \
                int kc_ = (ks_) * 2 + (mi >> 1);                                       \
                ldsm4(aF[buf][a_], (asB_) + mr_ * 128 + ((kc_ ^ (mr_ & 7)) << 4));     \
            }                                                                          \
            _Pragma("unroll")                                                          \
            for (int q_ = 0; q_ < 2; q_++) {                                           \
                int nr_ = wn + q_ * 16 + ((mi >> 1) << 3) + lr;                        \
                int kc_ = (ks_) * 2 + (mi & 1);                                        \
                ldsm4(bF[buf][q_], (bsB_) + nr_ * 128 + ((kc_ ^ (nr_ & 7)) << 4));     \
            }                                                                          \
        } while (0)

    float acc[4][4][4] = {};

    int s = 0, phv = 0;         // consumer cursor
    int sp = 2;                 // producer's next stage (tid 0 only)
    for (int it = 0; it < KT; ++it) {
        __syncthreads();        // all reads of the stage being reissued done
        if (tid == 0 && it + 2 < KT) {
            uint32_t fm = sbA + 8 * sp;
            uint32_t ds = SD + sp * STAGEB;
            mbar_expect(fm, STAGEB);
            tma2d(ds,       &tmA, (it + 2) * BK, m0, fm);
            tma2d(ds + ASZ, &tmB, (it + 2) * BK, n0, fm);
            sp = (sp == STG - 1) ? 0 : sp + 1;
        }
        mbar_wait(sbA + 8 * s, phv);

        uint32_t asB = SD + s * STAGEB;
        uint32_t bsB = asB + ASZ;

        LDFRAGS(0, asB, bsB, 0);
        #pragma unroll
        for (int ks = 0; ks < 4; ++ks) {
            if (ks < 3) LDFRAGS((ks + 1) & 1, asB, bsB, ks + 1);
            int bu = ks & 1;
            #pragma unroll
            for (int a = 0; a < 4; a++)
                #pragma unroll
                for (int b = 0; b < 4; b++)
                    mma16816(acc[a][b], aF[bu][a], &bF[bu][b >> 1][(b & 1) * 2]);
        }
        if (++s == STG) { s = 0; phv ^= 1; }
    }

    // epilogue: add fp32 bias, store fp32 tiles
    int row0 = m0 + wm + (lid >> 2);
    int col0 = n0 + wn + (lid & 3) * 2;
    #pragma unroll
    for (int b = 0; b < 4; b++) {
        float bv0 = g_bias[col0 + b * 8];
        float bv1 = g_bias[col0 + b * 8 + 1];
        #pragma unroll
        for (int a = 0; a < 4; a++) {
            float* p0 = out + (size_t)(row0 + a * 16) * OUTF_ + col0 + b * 8;
            float* p1 = p0 + (size_t)8 * OUTF_;
            *reinterpret_cast<float2*>(p0) =
                make_float2(acc[a][b][0] + bv0, acc[a][b][1] + bv1);
            *reinterpret_cast<float2*>(p1) =
                make_float2(acc[a][b][2] + bv0, acc[a][b][3] + bv1);
        }
    }
}

// ---------------------------------------------------------------------------
typedef CUresult (CUDAAPI *PFN_tmEncode)(
    CUtensorMap*, CUtensorMapDataType, cuuint32_t, void*,
    const cuuint64_t*, const cuuint64_t*, const cuuint32_t*, const cuuint32_t*,
    CUtensorMapInterleave, CUtensorMapSwizzle, CUtensorMapL2promotion,
    CUtensorMapFloatOOBfill);

extern "C" void kernel_launch(void* const* d_in, const int* in_sizes, int n_in,
                              void* d_out, int out_size) {
    const float* x  = (const float*)d_in[0];   // (4,2048,1024)
    const float* sw = (const float*)d_in[1];   // (1024,1024,12)
    const float* bw = (const float*)d_in[2];   // (1024,1024)
    float* out = (float*)d_out;                // (4,2048,1024)

    CUtensorMap tmA, tmB;
    PFN_tmEncode enc = nullptr;
    cudaDriverEntryPointQueryResult qr = cudaDriverEntryPointSymbolNotFound;
    cudaGetDriverEntryPoint("cuTensorMapEncodeTiled", (void**)&enc,
                            cudaEnableDefault, &qr);
    void *pA = nullptr, *pW = nullptr;
    cudaGetSymbolAddress(&pA, g_A);
    cudaGetSymbolAddress(&pW, g_W);

    cuuint64_t dimsA[2] = {KD, MTOT};
    cuuint64_t strA[1]  = {KD * 2};
    cuuint32_t boxA[2]  = {BK, BM};
    cuuint32_t el[2]    = {1, 1};
    enc(&tmA, CU_TENSOR_MAP_DATA_TYPE_FLOAT16, 2, pA, dimsA, strA, boxA, el,
        CU_TENSOR_MAP_INTERLEAVE_NONE, CU_TENSOR_MAP_SWIZZLE_128B,
        CU_TENSOR_MAP_L2_PROMOTION_L2_128B, CU_TENSOR_MAP_FLOAT_OOB_FILL_NONE);

    cuuint64_t dimsB[2] = {KD, OUTF_};
    cuuint64_t strB[1]  = {KD * 2};
    cuuint32_t boxB[2]  = {BK, BN};
    enc(&tmB, CU_TENSOR_MAP_DATA_TYPE_FLOAT16, 2, pW, dimsB, strB, boxB, el,
        CU_TENSOR_MAP_INTERLEAVE_NONE, CU_TENSOR_MAP_SWIZZLE_128B,
        CU_TENSOR_MAP_L2_PROMOTION_L2_128B, CU_TENSOR_MAP_FLOAT_OOB_FILL_NONE);

    cudaFuncSetAttribute(kan_gemm, cudaFuncAttributeMaxDynamicSharedMemorySize, SMEMSZ);

    build_W<<<(OUTF_ * INF_) / 256, 256>>>(sw, bw);
    sum_bias<<<4, 256>>>();
    build_A<<<(MTOT * INF_) / 256, 256>>>(x);
    dim3 grid(OUTF_ / BN, MTOT / BM);   // x = N tile (fast, 16) -> A L2 reuse
    kan_gemm<<<grid, 128, SMEMSZ>>>(tmA, tmB, out);
}